// round 13
// baseline (speedup 1.0000x reference)
#include <cuda_runtime.h>

// SSIM loss, fused separable 11x11 Gaussian depthwise conv (4 fields:
// mu1, mu2, E[x^2+y^2], E[x*y]).  Tile 128x48, 416 threads, 2 blocks/SM
// (26 warps/SM).  Field-interleaved smem (float4/pixel): STS.128 vertical,
// LDS.128 horizontal (VSTRIDE=139, quad step 3 -> conflict-free).
// Pairwise division + depth-1 LDG prefetch.
// Single kernel: per-tile partials + last-block deterministic finalize.

#define PLANE      512
#define TW         128
#define TH         48
#define VCOLS      138         // TW + 10 (x halo)
#define VSTRIDE    139         // float4 slots per smem row (odd -> conflict-free)
#define NTHREADS   416
#define NTILE_X    4           // 512/128
#define NTILE_Y    11          // ceil(512/48)
#define NPLANES    96          // 32*3
#define NPART      (NTILE_X*NTILE_Y*NPLANES)   // 4224

__device__ float g_partial[NPART];
__device__ unsigned int g_count;    // zero-init; reset by last block each replay

// Gaussian(11, sigma=1.5), normalized. Compile-time literals -> FFMA-imm (rt=1).
__device__ __forceinline__ float gw(int k) {
    constexpr float KW[11] = {
        0.0010284f, 0.0075988f, 0.0360008f, 0.1093607f, 0.2130055f,
        0.2660117f,
        0.2130055f, 0.1093607f, 0.0360008f, 0.0075988f, 0.0010284f
    };
    return KW[k];
}

__global__ void __launch_bounds__(NTHREADS, 2)
ssim_kernel(const float* __restrict__ img1, const float* __restrict__ img2,
            float* __restrict__ out)
{
    extern __shared__ float4 sm4[];   // TH * VSTRIDE float4 = 106752 B

    const int tid = threadIdx.x;
    const int x0  = blockIdx.x * TW;
    const int y0  = blockIdx.y * TH;
    const float* __restrict__ p1 = img1 + (size_t)blockIdx.z * (PLANE * PLANE);
    const float* __restrict__ p2 = img2 + (size_t)blockIdx.z * (PLANE * PLANE);

    // ---------------- Vertical pass (global -> smem), 4 fields ----------------
    // 414 tasks: column c (0..137) x strip (0..2), strip = 16 output rows.
    if (tid < VCOLS * 3) {
        const int c     = tid % VCOLS;
        const int strip = tid / VCOLS;
        const int gx    = x0 + c - 5;
        const bool xok  = ((unsigned)gx < (unsigned)PLANE);
        const int ybase = y0 + strip * 16 - 5;

        float m1[16], m2[16], es[16], ep[16];
        #pragma unroll
        for (int r = 0; r < 16; ++r) { m1[r]=0.f; m2[r]=0.f; es[r]=0.f; ep[r]=0.f; }

        // depth-1 software pipeline on the global loads
        bool ok0 = xok && ((unsigned)ybase < (unsigned)PLANE);
        int  idx0 = ybase * PLANE + gx;
        float a1c = ok0 ? __ldg(p1 + idx0) : 0.f;
        float a2c = ok0 ? __ldg(p2 + idx0) : 0.f;

        #pragma unroll
        for (int j = 0; j < 26; ++j) {
            float a1n = 0.f, a2n = 0.f;
            if (j < 25) {
                const int gy = ybase + j + 1;
                const bool ok = xok && ((unsigned)gy < (unsigned)PLANE);
                const int idx = gy * PLANE + gx;
                a1n = ok ? __ldg(p1 + idx) : 0.f;
                a2n = ok ? __ldg(p2 + idx) : 0.f;
            }
            const float a1 = a1c, a2 = a2c;
            float qs = fmaf(a1, a1, a2 * a2);   // x^2 + y^2
            float qp = a1 * a2;                 // x * y
            #pragma unroll
            for (int k = 0; k < 11; ++k) {
                const int o = j - k;
                if (o >= 0 && o < 16) {
                    m1[o] = fmaf(gw(k), a1, m1[o]);
                    m2[o] = fmaf(gw(k), a2, m2[o]);
                    es[o] = fmaf(gw(k), qs, es[o]);
                    ep[o] = fmaf(gw(k), qp, ep[o]);
                }
            }
            a1c = a1n; a2c = a2n;
        }
        float4* dst = sm4 + (strip * 16) * VSTRIDE + c;
        #pragma unroll
        for (int r = 0; r < 16; ++r)
            dst[r * VSTRIDE] = make_float4(m1[r], m2[r], es[r], ep[r]);
    }
    __syncthreads();

    // ---------------- Horizontal pass (smem -> SSIM map -> local sum) --------
    // 384 tasks: seg=(tid>>4)&7 (8 segs of 16 cols), row=(tid&15)+16*(tid>>7).
    // LDS.128 8-lane phases = 8 consecutive rows of one seg; quad step
    // 139 mod 8 = 3 (odd) -> conflict-free.
    float lsum = 0.f;
    if (tid < TH * 8) {
        const int seg = (tid >> 4) & 7;
        const int row = (tid & 15) + ((tid >> 7) << 4);
        const float4* rp = sm4 + row * VSTRIDE + seg * 16;

        float m1[16], m2[16], es[16], ep[16];
        #pragma unroll
        for (int o = 0; o < 16; ++o) { m1[o]=0.f; m2[o]=0.f; es[o]=0.f; ep[o]=0.f; }

        #pragma unroll
        for (int j = 0; j < 26; ++j) {
            const float4 v = rp[j];
            #pragma unroll
            for (int k = 0; k < 11; ++k) {
                const int o = j - k;
                if (o >= 0 && o < 16) {
                    m1[o] = fmaf(gw(k), v.x, m1[o]);
                    m2[o] = fmaf(gw(k), v.y, m2[o]);
                    es[o] = fmaf(gw(k), v.z, es[o]);
                    ep[o] = fmaf(gw(k), v.w, ep[o]);
                }
            }
        }

        const int gy = y0 + row;
        if (gy < PLANE) {
            const float C1 = 0.0001f;   // (0.01)^2
            const float C2 = 0.0009f;   // (0.03)^2
            float num[16], den[16];
            #pragma unroll
            for (int o = 0; o < 16; ++o) {
                float mu1 = m1[o], mu2 = m2[o];
                float mu12  = mu1 * mu2;                   // mu1*mu2
                float musqs = fmaf(mu1, mu1, mu2 * mu2);   // mu1^2 + mu2^2
                float s12   = ep[o] - mu12;                // sigma12
                float ssum  = es[o] - musqs;               // sigma1^2 + sigma2^2
                num[o] = fmaf(2.f, mu12, C1) * fmaf(2.f, s12, C2);
                den[o] = (musqs + C1) * (ssum + C2);
            }
            // pairwise combine: a/b + c/d = (a*d + c*b) / (b*d) -> 8 divides
            #pragma unroll
            for (int o = 0; o < 16; o += 2) {
                float nn = fmaf(num[o], den[o + 1], num[o + 1] * den[o]);
                float dd = den[o] * den[o + 1];
                lsum += __fdividef(nn, dd);
            }
        }
    }

    // ---------------- Block reduction (fixed order, deterministic) -----------
    #pragma unroll
    for (int off = 16; off > 0; off >>= 1)
        lsum += __shfl_down_sync(0xffffffffu, lsum, off);

    __shared__ float wsum[NTHREADS / 32];
    const int wid = tid >> 5, lane = tid & 31;
    if (lane == 0) wsum[wid] = lsum;
    __syncthreads();

    const int bid = ((int)blockIdx.z * NTILE_Y + (int)blockIdx.y) * NTILE_X + (int)blockIdx.x;
    if (tid == 0) {
        float s = 0.f;
        #pragma unroll
        for (int w = 0; w < NTHREADS / 32; ++w) s += wsum[w];
        g_partial[bid] = s;
    }

    // ---------------- Last-block deterministic finalize ----------------------
    __shared__ bool isLast;
    if (tid == 0) {
        __threadfence();
        unsigned old = atomicAdd(&g_count, 1u);
        isLast = (old == (unsigned)(NPART - 1));
    }
    __syncthreads();
    if (isLast) {
        __threadfence();
        double s = 0.0;
        for (int i = tid; i < NPART; i += NTHREADS)
            s += (double)__ldcg(g_partial + i);     // fixed per-thread order
        __shared__ double ds[NTHREADS];
        ds[tid] = s;
        __syncthreads();
        if (tid < 208) ds[tid] += ds[tid + 208]; __syncthreads();
        if (tid < 104) ds[tid] += ds[tid + 104]; __syncthreads();
        if (tid <  52) ds[tid] += ds[tid +  52]; __syncthreads();
        if (tid <  26) ds[tid] += ds[tid +  26]; __syncthreads();
        if (tid <  13) ds[tid] += ds[tid +  13]; __syncthreads();
        if (tid == 0) {
            double tot = 0.0;
            #pragma unroll
            for (int w = 0; w < 13; ++w) tot += ds[w];
            const double N = 32.0 * 3.0 * 512.0 * 512.0;
            out[0] = (float)(1.0 - tot / N);
            g_count = 0;                             // reset for next graph replay
        }
    }
}

extern "C" void kernel_launch(void* const* d_in, const int* in_sizes, int n_in,
                              void* d_out, int out_size)
{
    const float* img1 = (const float*)d_in[0];
    const float* img2 = (const float*)d_in[1];
    float* out = (float*)d_out;

    const int smem = TH * VSTRIDE * (int)sizeof(float4);   // 106752 B
    cudaFuncSetAttribute(ssim_kernel, cudaFuncAttributeMaxDynamicSharedMemorySize, smem);

    dim3 grid(NTILE_X, NTILE_Y, NPLANES);
    ssim_kernel<<<grid, NTHREADS, smem>>>(img1, img2, out);
}

// round 14
// speedup vs baseline: 1.6185x; 1.6185x over previous
#include <cuda_runtime.h>

// SSIM loss, fused separable 11x11 Gaussian depthwise conv (4 fields:
// mu1, mu2, E[x^2+y^2], E[x*y]).  Tile 64x48, 224 threads, 3 blocks/SM.
// Field-interleaved smem (float4/pixel): STS.128 vertical, LDS.128 horizontal.
// R12 champion + depth-2 LDG software pipeline in the vertical pass.
// Single kernel: per-tile partials + last-block deterministic finalize.

#define PLANE      512
#define TW         64
#define TH         48
#define VCOLS      74          // TW + 10 (x halo)
#define VSTRIDE    75          // float4 slots per smem row (odd -> conflict-free)
#define NTHREADS   224
#define NTILE_X    8           // 512/64
#define NTILE_Y    11          // ceil(512/48)
#define NPLANES    96          // 32*3
#define NPART      (NTILE_X*NTILE_Y*NPLANES)   // 8448

__device__ float g_partial[NPART];
__device__ unsigned int g_count;    // zero-init; reset by last block each replay

// Gaussian(11, sigma=1.5), normalized. Compile-time literals -> FFMA-imm (rt=1).
__device__ __forceinline__ float gw(int k) {
    constexpr float KW[11] = {
        0.0010284f, 0.0075988f, 0.0360008f, 0.1093607f, 0.2130055f,
        0.2660117f,
        0.2130055f, 0.1093607f, 0.0360008f, 0.0075988f, 0.0010284f
    };
    return KW[k];
}

__global__ void __launch_bounds__(NTHREADS, 3)
ssim_kernel(const float* __restrict__ img1, const float* __restrict__ img2,
            float* __restrict__ out)
{
    extern __shared__ float4 sm4[];   // TH * VSTRIDE float4 = 57600 B

    const int tid = threadIdx.x;
    const int x0  = blockIdx.x * TW;
    const int y0  = blockIdx.y * TH;
    const float* __restrict__ p1 = img1 + (size_t)blockIdx.z * (PLANE * PLANE);
    const float* __restrict__ p2 = img2 + (size_t)blockIdx.z * (PLANE * PLANE);

    // ---------------- Vertical pass (global -> smem), 4 fields ----------------
    // 222 tasks: column c (0..73) x strip (0..2), strip = 16 output rows.
    if (tid < VCOLS * 3) {
        const int c     = tid % VCOLS;
        const int strip = tid / VCOLS;
        const int gx    = x0 + c - 5;
        const bool xok  = ((unsigned)gx < (unsigned)PLANE);
        const int ybase = y0 + strip * 16 - 5;

        float m1[16], m2[16], es[16], ep[16];
        #pragma unroll
        for (int r = 0; r < 16; ++r) { m1[r]=0.f; m2[r]=0.f; es[r]=0.f; ep[r]=0.f; }

        // depth-2 software pipeline on the global loads
        float a1b[2], a2b[2];
        #pragma unroll
        for (int q = 0; q < 2; ++q) {
            const int gy = ybase + q;
            const bool ok = xok && ((unsigned)gy < (unsigned)PLANE);
            const int idx = gy * PLANE + gx;
            a1b[q] = ok ? __ldg(p1 + idx) : 0.f;
            a2b[q] = ok ? __ldg(p2 + idx) : 0.f;
        }

        #pragma unroll
        for (int j = 0; j < 26; ++j) {
            const float a1 = a1b[j & 1];
            const float a2 = a2b[j & 1];
            if (j < 24) {
                const int gy = ybase + j + 2;
                const bool ok = xok && ((unsigned)gy < (unsigned)PLANE);
                const int idx = gy * PLANE + gx;
                a1b[j & 1] = ok ? __ldg(p1 + idx) : 0.f;
                a2b[j & 1] = ok ? __ldg(p2 + idx) : 0.f;
            }
            float qs = fmaf(a1, a1, a2 * a2);   // x^2 + y^2
            float qp = a1 * a2;                 // x * y
            #pragma unroll
            for (int k = 0; k < 11; ++k) {
                const int o = j - k;
                if (o >= 0 && o < 16) {
                    m1[o] = fmaf(gw(k), a1, m1[o]);
                    m2[o] = fmaf(gw(k), a2, m2[o]);
                    es[o] = fmaf(gw(k), qs, es[o]);
                    ep[o] = fmaf(gw(k), qp, ep[o]);
                }
            }
        }
        float4* dst = sm4 + (strip * 16) * VSTRIDE + c;
        #pragma unroll
        for (int r = 0; r < 16; ++r)
            dst[r * VSTRIDE] = make_float4(m1[r], m2[r], es[r], ep[r]);
    }
    __syncthreads();

    // ---------------- Horizontal pass (smem -> SSIM map -> local sum) --------
    // 192 tasks: seg=(tid>>4)&3, row=(tid&15)+16*(tid>>6).  LDS.128 phases are
    // 8 consecutive rows; quad step 75 mod 8 = 3 (odd) -> conflict-free.
    float lsum = 0.f;
    if (tid < TH * 4) {
        const int seg = (tid >> 4) & 3;
        const int row = (tid & 15) + ((tid >> 6) << 4);
        const float4* rp = sm4 + row * VSTRIDE + seg * 16;

        float m1[16], m2[16], es[16], ep[16];
        #pragma unroll
        for (int o = 0; o < 16; ++o) { m1[o]=0.f; m2[o]=0.f; es[o]=0.f; ep[o]=0.f; }

        #pragma unroll
        for (int j = 0; j < 26; ++j) {
            const float4 v = rp[j];
            #pragma unroll
            for (int k = 0; k < 11; ++k) {
                const int o = j - k;
                if (o >= 0 && o < 16) {
                    m1[o] = fmaf(gw(k), v.x, m1[o]);
                    m2[o] = fmaf(gw(k), v.y, m2[o]);
                    es[o] = fmaf(gw(k), v.z, es[o]);
                    ep[o] = fmaf(gw(k), v.w, ep[o]);
                }
            }
        }

        const int gy = y0 + row;
        if (gy < PLANE) {
            const float C1 = 0.0001f;   // (0.01)^2
            const float C2 = 0.0009f;   // (0.03)^2
            float num[16], den[16];
            #pragma unroll
            for (int o = 0; o < 16; ++o) {
                float mu1 = m1[o], mu2 = m2[o];
                float mu12  = mu1 * mu2;                   // mu1*mu2
                float musqs = fmaf(mu1, mu1, mu2 * mu2);   // mu1^2 + mu2^2
                float s12   = ep[o] - mu12;                // sigma12
                float ssum  = es[o] - musqs;               // sigma1^2 + sigma2^2
                num[o] = fmaf(2.f, mu12, C1) * fmaf(2.f, s12, C2);
                den[o] = (musqs + C1) * (ssum + C2);
            }
            // pairwise combine: a/b + c/d = (a*d + c*b) / (b*d) -> 8 divides
            #pragma unroll
            for (int o = 0; o < 16; o += 2) {
                float nn = fmaf(num[o], den[o + 1], num[o + 1] * den[o]);
                float dd = den[o] * den[o + 1];
                lsum += __fdividef(nn, dd);
            }
        }
    }

    // ---------------- Block reduction (fixed order, deterministic) -----------
    #pragma unroll
    for (int off = 16; off > 0; off >>= 1)
        lsum += __shfl_down_sync(0xffffffffu, lsum, off);

    __shared__ float wsum[NTHREADS / 32];
    const int wid = tid >> 5, lane = tid & 31;
    if (lane == 0) wsum[wid] = lsum;
    __syncthreads();

    const int bid = ((int)blockIdx.z * NTILE_Y + (int)blockIdx.y) * NTILE_X + (int)blockIdx.x;
    if (tid == 0) {
        float s = 0.f;
        #pragma unroll
        for (int w = 0; w < NTHREADS / 32; ++w) s += wsum[w];
        g_partial[bid] = s;
    }

    // ---------------- Last-block deterministic finalize ----------------------
    __shared__ bool isLast;
    if (tid == 0) {
        __threadfence();
        unsigned old = atomicAdd(&g_count, 1u);
        isLast = (old == (unsigned)(NPART - 1));
    }
    __syncthreads();
    if (isLast) {
        __threadfence();
        double s = 0.0;
        for (int i = tid; i < NPART; i += NTHREADS)
            s += (double)__ldcg(g_partial + i);     // fixed per-thread order
        __shared__ double ds[NTHREADS];
        ds[tid] = s;
        __syncthreads();
        if (tid < 112) ds[tid] += ds[tid + 112]; __syncthreads();
        if (tid <  56) ds[tid] += ds[tid +  56]; __syncthreads();
        if (tid <  28) ds[tid] += ds[tid +  28]; __syncthreads();
        if (tid <  14) ds[tid] += ds[tid +  14]; __syncthreads();
        if (tid <   7) ds[tid] += ds[tid +   7]; __syncthreads();
        if (tid == 0) {
            double tot = 0.0;
            #pragma unroll
            for (int w = 0; w < 7; ++w) tot += ds[w];
            const double N = 32.0 * 3.0 * 512.0 * 512.0;
            out[0] = (float)(1.0 - tot / N);
            g_count = 0;                             // reset for next graph replay
        }
    }
}

extern "C" void kernel_launch(void* const* d_in, const int* in_sizes, int n_in,
                              void* d_out, int out_size)
{
    const float* img1 = (const float*)d_in[0];
    const float* img2 = (const float*)d_in[1];
    float* out = (float*)d_out;

    const int smem = TH * VSTRIDE * (int)sizeof(float4);   // 57600 B
    cudaFuncSetAttribute(ssim_kernel, cudaFuncAttributeMaxDynamicSharedMemorySize, smem);

    dim3 grid(NTILE_X, NTILE_Y, NPLANES);
    ssim_kernel<<<grid, NTHREADS, smem>>>(img1, img2, out);
}

// round 15
// speedup vs baseline: 1.6347x; 1.0100x over previous
#include <cuda_runtime.h>

// SSIM loss, fused separable 11x11 Gaussian depthwise conv (4 fields:
// mu1, mu2, E[x^2+y^2], E[x*y]).  Tile 64x48, 224 threads, 3 blocks/SM.
// Field-interleaved smem (float4/pixel): STS.128 vertical, LDS.128 horizontal.
// R12 champion (depth-1 prefetch, pairwise division) + float4 finalize.
// Single kernel: per-tile partials + last-block deterministic finalize.

#define PLANE      512
#define TW         64
#define TH         48
#define VCOLS      74          // TW + 10 (x halo)
#define VSTRIDE    75          // float4 slots per smem row (odd -> conflict-free)
#define NTHREADS   224
#define NTILE_X    8           // 512/64
#define NTILE_Y    11          // ceil(512/48)
#define NPLANES    96          // 32*3
#define NPART      (NTILE_X*NTILE_Y*NPLANES)   // 8448 (divisible by 4)

__device__ float g_partial[NPART];
__device__ unsigned int g_count;    // zero-init; reset by last block each replay

// Gaussian(11, sigma=1.5), normalized. Compile-time literals -> FFMA-imm (rt=1).
__device__ __forceinline__ float gw(int k) {
    constexpr float KW[11] = {
        0.0010284f, 0.0075988f, 0.0360008f, 0.1093607f, 0.2130055f,
        0.2660117f,
        0.2130055f, 0.1093607f, 0.0360008f, 0.0075988f, 0.0010284f
    };
    return KW[k];
}

__global__ void __launch_bounds__(NTHREADS, 3)
ssim_kernel(const float* __restrict__ img1, const float* __restrict__ img2,
            float* __restrict__ out)
{
    extern __shared__ float4 sm4[];   // TH * VSTRIDE float4 = 57600 B

    const int tid = threadIdx.x;
    const int x0  = blockIdx.x * TW;
    const int y0  = blockIdx.y * TH;
    const float* __restrict__ p1 = img1 + (size_t)blockIdx.z * (PLANE * PLANE);
    const float* __restrict__ p2 = img2 + (size_t)blockIdx.z * (PLANE * PLANE);

    // ---------------- Vertical pass (global -> smem), 4 fields ----------------
    // 222 tasks: column c (0..73) x strip (0..2), strip = 16 output rows.
    if (tid < VCOLS * 3) {
        const int c     = tid % VCOLS;
        const int strip = tid / VCOLS;
        const int gx    = x0 + c - 5;
        const bool xok  = ((unsigned)gx < (unsigned)PLANE);
        const int ybase = y0 + strip * 16 - 5;

        float m1[16], m2[16], es[16], ep[16];
        #pragma unroll
        for (int r = 0; r < 16; ++r) { m1[r]=0.f; m2[r]=0.f; es[r]=0.f; ep[r]=0.f; }

        // depth-1 software pipeline on the global loads
        bool ok0 = xok && ((unsigned)ybase < (unsigned)PLANE);
        int  idx0 = ybase * PLANE + gx;
        float a1c = ok0 ? __ldg(p1 + idx0) : 0.f;
        float a2c = ok0 ? __ldg(p2 + idx0) : 0.f;

        #pragma unroll
        for (int j = 0; j < 26; ++j) {
            float a1n = 0.f, a2n = 0.f;
            if (j < 25) {
                const int gy = ybase + j + 1;
                const bool ok = xok && ((unsigned)gy < (unsigned)PLANE);
                const int idx = gy * PLANE + gx;
                a1n = ok ? __ldg(p1 + idx) : 0.f;
                a2n = ok ? __ldg(p2 + idx) : 0.f;
            }
            const float a1 = a1c, a2 = a2c;
            float qs = fmaf(a1, a1, a2 * a2);   // x^2 + y^2
            float qp = a1 * a2;                 // x * y
            #pragma unroll
            for (int k = 0; k < 11; ++k) {
                const int o = j - k;
                if (o >= 0 && o < 16) {
                    m1[o] = fmaf(gw(k), a1, m1[o]);
                    m2[o] = fmaf(gw(k), a2, m2[o]);
                    es[o] = fmaf(gw(k), qs, es[o]);
                    ep[o] = fmaf(gw(k), qp, ep[o]);
                }
            }
            a1c = a1n; a2c = a2n;
        }
        float4* dst = sm4 + (strip * 16) * VSTRIDE + c;
        #pragma unroll
        for (int r = 0; r < 16; ++r)
            dst[r * VSTRIDE] = make_float4(m1[r], m2[r], es[r], ep[r]);
    }
    __syncthreads();

    // ---------------- Horizontal pass (smem -> SSIM map -> local sum) --------
    // 192 tasks: seg=(tid>>4)&3, row=(tid&15)+16*(tid>>6).  LDS.128 phases are
    // 8 consecutive rows; quad step 75 mod 8 = 3 (odd) -> conflict-free.
    float lsum = 0.f;
    if (tid < TH * 4) {
        const int seg = (tid >> 4) & 3;
        const int row = (tid & 15) + ((tid >> 6) << 4);
        const float4* rp = sm4 + row * VSTRIDE + seg * 16;

        float m1[16], m2[16], es[16], ep[16];
        #pragma unroll
        for (int o = 0; o < 16; ++o) { m1[o]=0.f; m2[o]=0.f; es[o]=0.f; ep[o]=0.f; }

        #pragma unroll
        for (int j = 0; j < 26; ++j) {
            const float4 v = rp[j];
            #pragma unroll
            for (int k = 0; k < 11; ++k) {
                const int o = j - k;
                if (o >= 0 && o < 16) {
                    m1[o] = fmaf(gw(k), v.x, m1[o]);
                    m2[o] = fmaf(gw(k), v.y, m2[o]);
                    es[o] = fmaf(gw(k), v.z, es[o]);
                    ep[o] = fmaf(gw(k), v.w, ep[o]);
                }
            }
        }

        const int gy = y0 + row;
        if (gy < PLANE) {
            const float C1 = 0.0001f;   // (0.01)^2
            const float C2 = 0.0009f;   // (0.03)^2
            float num[16], den[16];
            #pragma unroll
            for (int o = 0; o < 16; ++o) {
                float mu1 = m1[o], mu2 = m2[o];
                float mu12  = mu1 * mu2;                   // mu1*mu2
                float musqs = fmaf(mu1, mu1, mu2 * mu2);   // mu1^2 + mu2^2
                float s12   = ep[o] - mu12;                // sigma12
                float ssum  = es[o] - musqs;               // sigma1^2 + sigma2^2
                num[o] = fmaf(2.f, mu12, C1) * fmaf(2.f, s12, C2);
                den[o] = (musqs + C1) * (ssum + C2);
            }
            // pairwise combine: a/b + c/d = (a*d + c*b) / (b*d) -> 8 divides
            #pragma unroll
            for (int o = 0; o < 16; o += 2) {
                float nn = fmaf(num[o], den[o + 1], num[o + 1] * den[o]);
                float dd = den[o] * den[o + 1];
                lsum += __fdividef(nn, dd);
            }
        }
    }

    // ---------------- Block reduction (fixed order, deterministic) -----------
    #pragma unroll
    for (int off = 16; off > 0; off >>= 1)
        lsum += __shfl_down_sync(0xffffffffu, lsum, off);

    __shared__ float wsum[NTHREADS / 32];
    const int wid = tid >> 5, lane = tid & 31;
    if (lane == 0) wsum[wid] = lsum;
    __syncthreads();

    const int bid = ((int)blockIdx.z * NTILE_Y + (int)blockIdx.y) * NTILE_X + (int)blockIdx.x;
    if (tid == 0) {
        float s = 0.f;
        #pragma unroll
        for (int w = 0; w < NTHREADS / 32; ++w) s += wsum[w];
        g_partial[bid] = s;
    }

    // ---------------- Last-block deterministic finalize ----------------------
    __shared__ bool isLast;
    if (tid == 0) {
        __threadfence();
        unsigned old = atomicAdd(&g_count, 1u);
        isLast = (old == (unsigned)(NPART - 1));
    }
    __syncthreads();
    if (isLast) {
        __threadfence();
        // float4 loads: 2112 vec4 / 224 threads, fixed per-thread order.
        const float4* p4 = (const float4*)g_partial;
        double s = 0.0;
        for (int i = tid; i < NPART / 4; i += NTHREADS) {
            float4 v = p4[i];
            s += ((double)v.x + (double)v.y) + ((double)v.z + (double)v.w);
        }
        __shared__ double ds[NTHREADS];
        ds[tid] = s;
        __syncthreads();
        if (tid < 112) ds[tid] += ds[tid + 112]; __syncthreads();
        if (tid <  56) ds[tid] += ds[tid +  56]; __syncthreads();
        if (tid <  28) ds[tid] += ds[tid +  28]; __syncthreads();
        if (tid <  14) ds[tid] += ds[tid +  14]; __syncthreads();
        if (tid <   7) ds[tid] += ds[tid +   7]; __syncthreads();
        if (tid == 0) {
            double tot = 0.0;
            #pragma unroll
            for (int w = 0; w < 7; ++w) tot += ds[w];
            const double N = 32.0 * 3.0 * 512.0 * 512.0;
            out[0] = (float)(1.0 - tot / N);
            g_count = 0;                             // reset for next graph replay
        }
    }
}

extern "C" void kernel_launch(void* const* d_in, const int* in_sizes, int n_in,
                              void* d_out, int out_size)
{
    const float* img1 = (const float*)d_in[0];
    const float* img2 = (const float*)d_in[1];
    float* out = (float*)d_out;

    const int smem = TH * VSTRIDE * (int)sizeof(float4);   // 57600 B
    cudaFuncSetAttribute(ssim_kernel, cudaFuncAttributeMaxDynamicSharedMemorySize, smem);

    dim3 grid(NTILE_X, NTILE_Y, NPLANES);
    ssim_kernel<<<grid, NTHREADS, smem>>>(img1, img2, out);
}